// round 8
// baseline (speedup 1.0000x reference)
#include <cuda_runtime.h>
#include <cuda_bf16.h>
#include <stdint.h>

// Problem constants (fixed shapes from setup_inputs)
#define B_SZ 32
#define C_SZ 512
#define T_PH 1024
#define TILE_T 1024       // frames per block tile
#define CPB    16         // channels per block
#define NT     256        // threads per block
#define NW     (NT / 32)  // warps per block

// Precomputed per-batch inclusive cumsum of durations.
__device__ int g_cum[B_SZ * T_PH];

// -----------------------------------------------------------------------------
// Kernel 1 (tiny): per-batch scan of durations -> g_cum, and mel_mask.
// One 1024-thread block per batch.
// -----------------------------------------------------------------------------
__global__ void __launch_bounds__(T_PH)
lr_scan_kernel(const int* __restrict__ durations,
               float* __restrict__ mask,   // nullptr if no mask
               int M)
{
    const int b    = blockIdx.x;
    const int tid  = threadIdx.x;
    const int lane = tid & 31;
    const int wid  = tid >> 5;

    __shared__ int wsum[32];

    int d = durations[b * T_PH + tid];
    int v = d;
    #pragma unroll
    for (int off = 1; off < 32; off <<= 1) {
        int n = __shfl_up_sync(0xFFFFFFFFu, v, off);
        if (lane >= off) v += n;
    }
    if (lane == 31) wsum[wid] = v;
    __syncthreads();
    if (wid == 0) {
        int w = wsum[lane];
        #pragma unroll
        for (int off = 1; off < 32; off <<= 1) {
            int n = __shfl_up_sync(0xFFFFFFFFu, w, off);
            if (lane >= off) w += n;
        }
        wsum[lane] = w;
    }
    __syncthreads();

    const int incl  = v + (wid ? wsum[wid - 1] : 0);
    const int total = wsum[31];
    g_cum[b * T_PH + tid] = incl;

    if (mask) {
        for (int t = tid; t < M; t += T_PH)
            mask[b * M + t] = (t >= total) ? 1.0f : 0.0f;
    }
}

// -----------------------------------------------------------------------------
// Kernel 2: the gather. Each block: (batch b, 1024-frame tile, 16 channels).
// Prologue is now just one coalesced 4KB cumsum load + one barrier.
// Steady state: binary search + distance-2 channel software pipeline
// (R6 configuration: __launch_bounds__(256,5), measured best).
// -----------------------------------------------------------------------------
__global__ void __launch_bounds__(NT, 5)
lr_gather_kernel(const float* __restrict__ x,
                 float* __restrict__ out,
                 int M)
{
    const int b   = blockIdx.z;
    const int c0  = blockIdx.y * CPB;
    const int t0  = blockIdx.x * TILE_T;
    const int tid = threadIdx.x;

    __shared__ int s_cum[T_PH];

    // ---- prologue: coalesced cumsum load (1 int4 per thread) ----
    reinterpret_cast<int4*>(s_cum)[tid] =
        reinterpret_cast<const int4*>(g_cum + b * T_PH)[tid];
    __syncthreads();

    const int total = s_cum[T_PH - 1];

    const int tl = t0 + tid * 4;
    if (tl >= M) return;   // (M % 4 == 0 guaranteed by dispatch -> tl+3 < M)

    // ---- binary search: p = searchsorted(cum, t, 'right'), clipped ----
    int p0 = 0, p1 = 0, p2 = 0, p3 = 0;
    #pragma unroll
    for (int step = T_PH / 2; step > 0; step >>= 1) {
        if (s_cum[p0 + step - 1] <= tl + 0) p0 += step;
        if (s_cum[p1 + step - 1] <= tl + 1) p1 += step;
        if (s_cum[p2 + step - 1] <= tl + 2) p2 += step;
        if (s_cum[p3 + step - 1] <= tl + 3) p3 += step;
    }
    p0 = min(p0, T_PH - 1);
    p1 = min(p1, T_PH - 1);
    p2 = min(p2, T_PH - 1);
    p3 = min(p3, T_PH - 1);

    const float m0 = (tl + 0 < total) ? 1.0f : 0.0f;
    const float m1 = (tl + 1 < total) ? 1.0f : 0.0f;
    const float m2 = (tl + 2 < total) ? 1.0f : 0.0f;
    const float m3 = (tl + 3 < total) ? 1.0f : 0.0f;

    // ---- gather: distance-2 channel software pipeline (32-bit offsets) ----
    const float* __restrict__ xb = x   + (b * C_SZ + c0) * T_PH;
    float*       __restrict__ ob = out + (b * C_SZ + c0) * M + tl;

    float a0, a1, a2, a3, e0, e1, e2, e3;
    {
        const float* __restrict__ xr0 = xb;
        const float* __restrict__ xr1 = xb + T_PH;
        a0 = __ldg(xr0 + p0); a1 = __ldg(xr0 + p1);
        a2 = __ldg(xr0 + p2); a3 = __ldg(xr0 + p3);
        e0 = __ldg(xr1 + p0); e1 = __ldg(xr1 + p1);
        e2 = __ldg(xr1 + p2); e3 = __ldg(xr1 + p3);
    }

    #pragma unroll
    for (int g = 0; g < CPB - 2; g += 2) {
        const float* __restrict__ xr0 = xb + (g + 2) * T_PH;
        const float* __restrict__ xr1 = xb + (g + 3) * T_PH;
        float n0 = __ldg(xr0 + p0), n1 = __ldg(xr0 + p1);
        float n2 = __ldg(xr0 + p2), n3 = __ldg(xr0 + p3);
        float q0 = __ldg(xr1 + p0), q1 = __ldg(xr1 + p1);
        float q2 = __ldg(xr1 + p2), q3 = __ldg(xr1 + p3);

        float4 oA = make_float4(a0 * m0, a1 * m1, a2 * m2, a3 * m3);
        float4 oE = make_float4(e0 * m0, e1 * m1, e2 * m2, e3 * m3);
        *reinterpret_cast<float4*>(ob + (g + 0) * M) = oA;
        *reinterpret_cast<float4*>(ob + (g + 1) * M) = oE;

        a0 = n0; a1 = n1; a2 = n2; a3 = n3;
        e0 = q0; e1 = q1; e2 = q2; e3 = q3;
    }

    {
        float4 oA = make_float4(a0 * m0, a1 * m1, a2 * m2, a3 * m3);
        float4 oE = make_float4(e0 * m0, e1 * m1, e2 * m2, e3 * m3);
        *reinterpret_cast<float4*>(ob + (CPB - 2) * M) = oA;
        *reinterpret_cast<float4*>(ob + (CPB - 1) * M) = oE;
    }
}

// -----------------------------------------------------------------------------
// Scalar fallback gather (only if M % 4 != 0).
// -----------------------------------------------------------------------------
__global__ void __launch_bounds__(NT)
lr_gather_scalar_kernel(const float* __restrict__ x,
                        float* __restrict__ out,
                        int M)
{
    const int b   = blockIdx.z;
    const int c0  = blockIdx.y * CPB;
    const int t   = blockIdx.x * NT + threadIdx.x;
    const int tid = threadIdx.x;

    __shared__ int s_cum[T_PH];
    reinterpret_cast<int4*>(s_cum)[tid] =
        reinterpret_cast<const int4*>(g_cum + b * T_PH)[tid];
    __syncthreads();

    if (t >= M) return;
    const int total = s_cum[T_PH - 1];

    int p = 0;
    #pragma unroll
    for (int step = T_PH / 2; step > 0; step >>= 1)
        if (s_cum[p + step - 1] <= t) p += step;
    p = min(p, T_PH - 1);
    const bool val = (t < total);

    const float* xb = x + (b * C_SZ + c0) * T_PH;
    float* ob = out + (b * C_SZ + c0) * M + t;
    #pragma unroll
    for (int cc = 0; cc < CPB; ++cc)
        ob[cc * M] = val ? __ldg(xb + cc * T_PH + p) : 0.0f;
}

// -----------------------------------------------------------------------------
// Launch
// -----------------------------------------------------------------------------
extern "C" void kernel_launch(void* const* d_in, const int* in_sizes, int n_in,
                              void* d_out, int out_size)
{
    const float* x         = (const float*)d_in[0];
    const int*   durations = (const int*)d_in[1];
    float* out = (float*)d_out;

    // Resolve M and layout: tuple  out[B,C,M] ++ mask[B,M] => B*M*(C+1);
    // fallback out-only => B*M*C.
    long long os = (long long)out_size;
    int M;
    float* mask_ptr = nullptr;
    if (os % ((long long)B_SZ * (C_SZ + 1)) == 0) {
        M = (int)(os / ((long long)B_SZ * (C_SZ + 1)));
        mask_ptr = out + (size_t)B_SZ * C_SZ * M;
    } else {
        M = (int)(os / ((long long)B_SZ * C_SZ));
    }

    // Pass 1: scan + mask (tiny)
    lr_scan_kernel<<<B_SZ, T_PH>>>(durations, mask_ptr, M);

    // Pass 2: gather
    if ((M & 3) == 0) {
        dim3 grid((M + TILE_T - 1) / TILE_T, C_SZ / CPB, B_SZ);
        lr_gather_kernel<<<grid, NT>>>(x, out, M);
    } else {
        dim3 grid((M + NT - 1) / NT, C_SZ / CPB, B_SZ);
        lr_gather_scalar_kernel<<<grid, NT>>>(x, out, M);
    }
}